// round 1
// baseline (speedup 1.0000x reference)
#include <cuda_runtime.h>
#include <math.h>

#define B_DIM   4
#define SEQ     2048
#define DIM_IN  1024
#define DIM_OUT 1024
#define DIM3    3072
#define NHEADS  16
#define HD      64
#define NTOK    (B_DIM * SEQ)        // 8192

// Scratch (allocation-free rule: __device__ globals)
__device__ float g_qkv[(size_t)NTOK * DIM3];   // [tok][3*1024] = [tok][which][head][hd]
__device__ float g_ctx[(size_t)NTOK * DIM_OUT];

// ---------------------------------------------------------------------------
// Tiled SGEMM: C[M,N] = A[M,K] @ B[K,N] (+ bias), fp32.
// BM=BN=128, BK=8, TM=TN=8, 256 threads.
// ---------------------------------------------------------------------------
template <int BM, int BN, int BK, int TM, int TN>
__global__ __launch_bounds__(256, 2)
void sgemm_kernel(int M, int N, int K,
                  const float* __restrict__ A,
                  const float* __restrict__ B,
                  float* __restrict__ C,
                  const float* __restrict__ bias) {
    __shared__ float As[BK * BM];   // transposed: As[k][m]
    __shared__ float Bs[BK * BN];   // Bs[k][n]

    const int cRow = blockIdx.y;
    const int cCol = blockIdx.x;
    const int tid  = threadIdx.x;

    const int threadRow = tid / (BN / TN);   // 0..15
    const int threadCol = tid % (BN / TN);   // 0..15

    A += (size_t)cRow * BM * K;
    B += cCol * BN;
    C += (size_t)cRow * BM * N + cCol * BN;

    const int innerRowA = tid / (BK / 4);    // 0..127
    const int innerColA = tid % (BK / 4);    // 0..1
    const int innerRowB = tid / (BN / 4);    // 0..7
    const int innerColB = tid % (BN / 4);    // 0..31

    float acc[TM * TN];
#pragma unroll
    for (int i = 0; i < TM * TN; i++) acc[i] = 0.0f;
    float regM[TM], regN[TN];

    for (int kb = 0; kb < K; kb += BK) {
        float4 a4 = *(const float4*)(A + (size_t)innerRowA * K + innerColA * 4);
        As[(innerColA * 4 + 0) * BM + innerRowA] = a4.x;
        As[(innerColA * 4 + 1) * BM + innerRowA] = a4.y;
        As[(innerColA * 4 + 2) * BM + innerRowA] = a4.z;
        As[(innerColA * 4 + 3) * BM + innerRowA] = a4.w;
        *(float4*)(Bs + innerRowB * BN + innerColB * 4) =
            *(const float4*)(B + (size_t)innerRowB * N + innerColB * 4);
        __syncthreads();
        A += BK;
        B += (size_t)BK * N;

#pragma unroll
        for (int d = 0; d < BK; d++) {
#pragma unroll
            for (int i = 0; i < TM; i += 4) {
                float4 t = *(const float4*)&As[d * BM + threadRow * TM + i];
                regM[i] = t.x; regM[i+1] = t.y; regM[i+2] = t.z; regM[i+3] = t.w;
            }
#pragma unroll
            for (int j = 0; j < TN; j += 4) {
                float4 t = *(const float4*)&Bs[d * BN + threadCol * TN + j];
                regN[j] = t.x; regN[j+1] = t.y; regN[j+2] = t.z; regN[j+3] = t.w;
            }
#pragma unroll
            for (int i = 0; i < TM; i++)
#pragma unroll
                for (int j = 0; j < TN; j++)
                    acc[i * TN + j] = fmaf(regM[i], regN[j], acc[i * TN + j]);
        }
        __syncthreads();
    }

#pragma unroll
    for (int i = 0; i < TM; i++) {
#pragma unroll
        for (int j = 0; j < TN; j++) {
            float v = acc[i * TN + j];
            if (bias) v += bias[cCol * BN + threadCol * TN + j];
            C[(size_t)(threadRow * TM + i) * N + threadCol * TN + j] = v;
        }
    }
}

// ---------------------------------------------------------------------------
// Flash attention, fp32. One block per (q-tile of 64, head, batch).
// 256 threads as 16x16 grid: thread owns 4 q-rows x 4 cols (scores) and
// 4 q-rows x 4 dims (output). K stored d-major for conflict-free float4 LDS.
// ---------------------------------------------------------------------------
#define LD 68   // 64 + 4 pad; 68*4B = 272B, multiple of 16 -> float4-aligned rows

__global__ __launch_bounds__(256)
void attn_kernel(const float* __restrict__ qkv, float* __restrict__ ctx) {
    const int qt  = blockIdx.x;            // 0..31
    const int h   = blockIdx.y;            // 0..15
    const int b   = blockIdx.z;            // 0..3
    const int tid = threadIdx.x;
    const int tx  = tid & 15;              // col group
    const int ty  = tid >> 4;              // row group

    extern __shared__ float sm[];
    float* Qs  = sm;                 // [64][LD]  Qs[r][d]
    float* Kts = sm + 64 * LD;       // [64][LD]  Kts[d][kv]   (d-major!)
    float* Vs  = sm + 2 * 64 * LD;   // [64][LD]  Vs[kv][d]
    float* Ps  = sm + 3 * 64 * LD;   // [64][LD]  Ps[r][kv]

    const int q0 = qt * 64;
    const size_t base = (size_t)b * SEQ * DIM3 + (size_t)h * HD;

    // Load Q tile (which = 0)
    for (int i = tid; i < 64 * 64; i += 256) {
        int r = i >> 6, d = i & 63;
        Qs[r * LD + d] = qkv[base + (size_t)(q0 + r) * DIM3 + d];
    }

    float m[4], l[4], o[16];
#pragma unroll
    for (int i = 0; i < 4; i++) { m[i] = -1e30f; l[i] = 0.0f; }
#pragma unroll
    for (int i = 0; i < 16; i++) o[i] = 0.0f;

    const float scale = 0.125f;  // 1/sqrt(64)

    for (int kt = 0; kt <= qt; kt++) {
        const int k0 = kt * 64;
        // Load K (which=1, transposed to d-major) and V (which=2)
        for (int i = tid; i < 64 * 64; i += 256) {
            int r = i >> 6, d = i & 63;
            size_t row = base + (size_t)(k0 + r) * DIM3;
            Kts[d * LD + r] = qkv[row + DIM_OUT + d];
            Vs[r * LD + d]  = qkv[row + 2 * DIM_OUT + d];
        }
        __syncthreads();

        // S = Q @ K^T  (thread: rows ty*4.., cols tx*4..)
        float s[16];
#pragma unroll
        for (int i = 0; i < 16; i++) s[i] = 0.0f;
        for (int d = 0; d < 64; d++) {
            float4 k4 = *(const float4*)&Kts[d * LD + tx * 4];
#pragma unroll
            for (int i = 0; i < 4; i++) {
                float q = Qs[(ty * 4 + i) * LD + d];
                s[i * 4 + 0] = fmaf(q, k4.x, s[i * 4 + 0]);
                s[i * 4 + 1] = fmaf(q, k4.y, s[i * 4 + 1]);
                s[i * 4 + 2] = fmaf(q, k4.z, s[i * 4 + 2]);
                s[i * 4 + 3] = fmaf(q, k4.w, s[i * 4 + 3]);
            }
        }

        // scale + causal mask (only diagonal tile needs masking)
        const bool diag = (kt == qt);
#pragma unroll
        for (int i = 0; i < 4; i++) {
            int r = ty * 4 + i;
#pragma unroll
            for (int j = 0; j < 4; j++) {
                int c = tx * 4 + j;
                float v = s[i * 4 + j] * scale;
                if (diag && c > r) v = -1e30f;
                s[i * 4 + j] = v;
            }
        }

        // online softmax per row (reduce across 16 tx lanes; groups are
        // 16-lane-aligned within the warp so xor 1..8 stays in-group)
#pragma unroll
        for (int i = 0; i < 4; i++) {
            float mx = fmaxf(fmaxf(s[i*4+0], s[i*4+1]), fmaxf(s[i*4+2], s[i*4+3]));
#pragma unroll
            for (int off = 8; off >= 1; off >>= 1)
                mx = fmaxf(mx, __shfl_xor_sync(0xffffffffu, mx, off));
            float mn    = fmaxf(m[i], mx);
            float alpha = __expf(m[i] - mn);
            float rs = 0.0f;
#pragma unroll
            for (int j = 0; j < 4; j++) {
                float p = __expf(s[i * 4 + j] - mn);
                s[i * 4 + j] = p;
                rs += p;
            }
#pragma unroll
            for (int off = 8; off >= 1; off >>= 1)
                rs += __shfl_xor_sync(0xffffffffu, rs, off);
            l[i] = l[i] * alpha + rs;
            m[i] = mn;
#pragma unroll
            for (int j = 0; j < 4; j++) o[i * 4 + j] *= alpha;
            *(float4*)&Ps[(ty * 4 + i) * LD + tx * 4] = *(float4*)&s[i * 4];
        }
        __syncthreads();

        // O += P @ V  (thread: rows ty*4.., dims tx*4..)
        for (int kv = 0; kv < 64; kv++) {
            float4 v4 = *(const float4*)&Vs[kv * LD + tx * 4];
#pragma unroll
            for (int i = 0; i < 4; i++) {
                float p = Ps[(ty * 4 + i) * LD + kv];
                o[i * 4 + 0] = fmaf(p, v4.x, o[i * 4 + 0]);
                o[i * 4 + 1] = fmaf(p, v4.y, o[i * 4 + 1]);
                o[i * 4 + 2] = fmaf(p, v4.z, o[i * 4 + 2]);
                o[i * 4 + 3] = fmaf(p, v4.w, o[i * 4 + 3]);
            }
        }
        __syncthreads();
    }

    // Normalize and write ctx[b, q, h*64 + d]
#pragma unroll
    for (int i = 0; i < 4; i++) {
        float inv = 1.0f / l[i];
        int r = q0 + ty * 4 + i;
        float4 v;
        v.x = o[i * 4 + 0] * inv;
        v.y = o[i * 4 + 1] * inv;
        v.z = o[i * 4 + 2] * inv;
        v.w = o[i * 4 + 3] * inv;
        *(float4*)&ctx[((size_t)b * SEQ + r) * DIM_OUT + h * HD + tx * 4] = v;
    }
}

// ---------------------------------------------------------------------------
extern "C" void kernel_launch(void* const* d_in, const int* in_sizes, int n_in,
                              void* d_out, int out_size) {
    const float* X     = (const float*)d_in[0];   // [4,2048,1024]
    const float* W_qkv = (const float*)d_in[1];   // [1024,3072]
    const float* W_out = (const float*)d_in[2];   // [1024,1024]
    const float* b_out = (const float*)d_in[3];   // [1024]
    float* out = (float*)d_out;                   // [4,2048,1024]

    float* qkv;
    float* ctx;
    cudaGetSymbolAddress((void**)&qkv, g_qkv);
    cudaGetSymbolAddress((void**)&ctx, g_ctx);

    // 1) QKV projection: [8192,1024] @ [1024,3072]
    {
        dim3 grid(DIM3 / 128, NTOK / 128);
        sgemm_kernel<128, 128, 8, 8, 8><<<grid, 256>>>(
            NTOK, DIM3, DIM_IN, X, W_qkv, qkv, nullptr);
    }

    // 2) Causal flash attention
    {
        static int smem_set = 0;
        const int smem_bytes = 4 * 64 * LD * sizeof(float);  // 69632
        cudaFuncSetAttribute(attn_kernel,
                             cudaFuncAttributeMaxDynamicSharedMemorySize,
                             smem_bytes);
        (void)smem_set;
        dim3 grid(SEQ / 64, NHEADS, B_DIM);
        attn_kernel<<<grid, 256, smem_bytes>>>(qkv, ctx);
    }

    // 3) Output projection + bias: [8192,1024] @ [1024,1024] + b
    {
        dim3 grid(DIM_OUT / 128, NTOK / 128);
        sgemm_kernel<128, 128, 8, 8, 8><<<grid, 256>>>(
            NTOK, DIM_OUT, DIM_OUT, ctx, W_out, out, b_out);
    }
}

// round 6
// speedup vs baseline: 1.5200x; 1.5200x over previous
#include <cuda_runtime.h>
#include <cuda_bf16.h>
#include <cstdint>
#include <math.h>

#define B_DIM   4
#define SEQ     2048
#define DIM_IN  1024
#define DIM_OUT 1024
#define DIM3    3072
#define NHEADS  16
#define HD      64
#define NTOK    (B_DIM * SEQ)        // 8192

// ---------------------------------------------------------------------------
// Scratch (__device__ globals: allocation-free rule)
// ---------------------------------------------------------------------------
__device__ float g_qkv[(size_t)NTOK * DIM3];
__device__ float g_ctx[(size_t)NTOK * DIM_OUT];
__device__ __nv_bfloat16 g_Xh[(size_t)NTOK * DIM_IN];
__device__ __nv_bfloat16 g_Xl[(size_t)NTOK * DIM_IN];
__device__ __nv_bfloat16 g_Ch[(size_t)NTOK * DIM_OUT];
__device__ __nv_bfloat16 g_Cl[(size_t)NTOK * DIM_OUT];
__device__ __nv_bfloat16 g_Wqkv_h[(size_t)DIM3 * DIM_IN];    // [N][K]
__device__ __nv_bfloat16 g_Wqkv_l[(size_t)DIM3 * DIM_IN];
__device__ __nv_bfloat16 g_Wout_h[(size_t)DIM_OUT * DIM_OUT];
__device__ __nv_bfloat16 g_Wout_l[(size_t)DIM_OUT * DIM_OUT];

// ---------------------------------------------------------------------------
// PTX helpers (compute_103-safe: mma.sync / ldmatrix / cp.async only)
// ---------------------------------------------------------------------------
__device__ __forceinline__ uint32_t smem_u32(const void* p) {
    uint32_t a;
    asm("{ .reg .u64 t; cvta.to.shared.u64 t, %1; cvt.u32.u64 %0, t; }"
        : "=r"(a) : "l"(p));
    return a;
}

__device__ __forceinline__ void cp16(uint32_t dst, const void* src) {
    asm volatile("cp.async.cg.shared.global [%0], [%1], 16;"
                 :: "r"(dst), "l"(src));
}
#define CP_COMMIT() asm volatile("cp.async.commit_group;")
#define CP_WAIT1()  asm volatile("cp.async.wait_group 1;")

__device__ __forceinline__ void ldsm4(uint32_t* r, uint32_t addr) {
    asm volatile("ldmatrix.sync.aligned.m8n8.x4.shared.b16 {%0,%1,%2,%3}, [%4];"
                 : "=r"(r[0]), "=r"(r[1]), "=r"(r[2]), "=r"(r[3]) : "r"(addr));
}

__device__ __forceinline__ void mma16816(float* c, const uint32_t* a, const uint32_t* b) {
    asm volatile(
        "mma.sync.aligned.m16n8k16.row.col.f32.bf16.bf16.f32 "
        "{%0,%1,%2,%3}, {%4,%5,%6,%7}, {%8,%9}, {%0,%1,%2,%3};"
        : "+f"(c[0]), "+f"(c[1]), "+f"(c[2]), "+f"(c[3])
        : "r"(a[0]), "r"(a[1]), "r"(a[2]), "r"(a[3]), "r"(b[0]), "r"(b[1]));
}

// ---------------------------------------------------------------------------
// Split fp32 -> bf16 hi/lo (row-major, same layout)
// ---------------------------------------------------------------------------
__global__ __launch_bounds__(256)
void split_rows_kernel(const float4* __restrict__ A, int n4,
                       uint2* __restrict__ H, uint2* __restrict__ L) {
    int i = blockIdx.x * 256 + threadIdx.x;
    if (i >= n4) return;
    float4 v = A[i];
    __nv_bfloat16 h0 = __float2bfloat16(v.x), h1 = __float2bfloat16(v.y);
    __nv_bfloat16 h2 = __float2bfloat16(v.z), h3 = __float2bfloat16(v.w);
    __nv_bfloat16 l0 = __float2bfloat16(v.x - __bfloat162float(h0));
    __nv_bfloat16 l1 = __float2bfloat16(v.y - __bfloat162float(h1));
    __nv_bfloat16 l2 = __float2bfloat16(v.z - __bfloat162float(h2));
    __nv_bfloat16 l3 = __float2bfloat16(v.w - __bfloat162float(h3));
    __nv_bfloat162 p01 = __halves2bfloat162(h0, h1);
    __nv_bfloat162 p23 = __halves2bfloat162(h2, h3);
    __nv_bfloat162 q01 = __halves2bfloat162(l0, l1);
    __nv_bfloat162 q23 = __halves2bfloat162(l2, l3);
    uint2 hh, ll;
    hh.x = *(uint32_t*)&p01; hh.y = *(uint32_t*)&p23;
    ll.x = *(uint32_t*)&q01; ll.y = *(uint32_t*)&q23;
    H[i] = hh;
    L[i] = ll;
}

// ---------------------------------------------------------------------------
// Transpose + split: W [K][N] fp32 -> Th/Tl [N][K] bf16
// ---------------------------------------------------------------------------
__global__ void transpose_split_kernel(const float* __restrict__ W, int K, int N,
                                       __nv_bfloat16* __restrict__ Th,
                                       __nv_bfloat16* __restrict__ Tl) {
    __shared__ float t[32][33];
    const int n0 = blockIdx.x * 32;
    const int k0 = blockIdx.y * 32;
    const int tx = threadIdx.x, ty = threadIdx.y;   // 32 x 8
#pragma unroll
    for (int i = 0; i < 32; i += 8)
        t[ty + i][tx] = W[(size_t)(k0 + ty + i) * N + n0 + tx];
    __syncthreads();
#pragma unroll
    for (int i = 0; i < 32; i += 8) {
        float v = t[tx][ty + i];
        __nv_bfloat16 h = __float2bfloat16(v);
        __nv_bfloat16 l = __float2bfloat16(v - __bfloat162float(h));
        Th[(size_t)(n0 + ty + i) * K + k0 + tx] = h;
        Tl[(size_t)(n0 + ty + i) * K + k0 + tx] = l;
    }
}

// ---------------------------------------------------------------------------
// HMMA GEMM: C[M,N] = A[M,K] @ B^T[N,K] (+bias), all operands pre-split bf16.
// 128x128 tile, BK=32, 8 warps (2m x 4n -> warp 64x32), double-buffered
// cp.async, 3-term bf16 split accumulated in f32.
// ---------------------------------------------------------------------------
#define BM 128
#define BN 128
#define BK 32
#define PADK 40                       // halves per row (80 B, conflict-free)
#define T_A  (BM * PADK * 2)          // 10240 B per tile
#define STAGE_B (4 * T_A)             // Ah | Al | Bh | Bl
#define GEMM_SMEM (2 * STAGE_B)       // 81920 B

__global__ __launch_bounds__(256, 1)
void hmma_gemm_kernel(int M, int N, int K,
                      const __nv_bfloat16* __restrict__ Ah,
                      const __nv_bfloat16* __restrict__ Al,
                      const __nv_bfloat16* __restrict__ Bh,
                      const __nv_bfloat16* __restrict__ Bl,
                      float* __restrict__ C,
                      const float* __restrict__ bias) {
    extern __shared__ char smem[];
    const uint32_t sbase = smem_u32(smem);
    const int tid  = threadIdx.x;
    const int lane = tid & 31;
    const int wid  = tid >> 5;
    const int m0 = blockIdx.y * BM;
    const int n0 = blockIdx.x * BN;
    const int warp_m = (wid & 1) * 64;
    const int warp_n = (wid >> 1) * 32;

    float c[4][4][4];
#pragma unroll
    for (int i = 0; i < 4; i++)
#pragma unroll
        for (int j = 0; j < 4; j++)
#pragma unroll
            for (int k = 0; k < 4; k++) c[i][j][k] = 0.0f;

    // ---- stage loader: 8 cp.async of 16B per thread ----
    auto load_stage = [&](int s, int kb) {
        const uint32_t st = sbase + s * STAGE_B;
#pragma unroll
        for (int r = 0; r < 2; r++) {
            const int i   = tid + r * 256;
            const int row = i >> 2;
            const int seg = i & 3;
            const uint32_t off = row * (PADK * 2) + seg * 16;
            const size_t ga = (size_t)(m0 + row) * K + kb + seg * 8;
            const size_t gb = (size_t)(n0 + row) * K + kb + seg * 8;
            cp16(st + off,             Ah + ga);
            cp16(st + T_A + off,       Al + ga);
            cp16(st + 2 * T_A + off,   Bh + gb);
            cp16(st + 3 * T_A + off,   Bl + gb);
        }
    };

    const int NKB = K / BK;
    load_stage(0, 0);
    CP_COMMIT();

    for (int kb = 0; kb < NKB; kb++) {
        if (kb + 1 < NKB) load_stage((kb + 1) & 1, (kb + 1) * BK);
        CP_COMMIT();
        CP_WAIT1();
        __syncthreads();

        const uint32_t st = sbase + (kb & 1) * STAGE_B;
#pragma unroll
        for (int ks = 0; ks < 2; ks++) {
            uint32_t ah[4][4], al[4][4], bh[4][2], bl[4][2];
            // A fragments (16x16 row-major): row = lane&15, colhalf = (lane>>4)*8
            const int arow = warp_m + (lane & 15);
            const int acol = ks * 16 + (lane >> 4) * 8;
#pragma unroll
            for (int mi = 0; mi < 4; mi++) {
                const uint32_t ad = st + ((arow + mi * 16) * PADK + acol) * 2;
                ldsm4(ah[mi], ad);
                ldsm4(al[mi], ad + T_A);
            }
            // B fragments: Bt[N][K]; x4 covers 16n x 16k
            const int bn = ((lane >> 3) & 1) * 8 + (lane & 7);
            const int bk = ks * 16 + (lane >> 4) * 8;
#pragma unroll
            for (int np = 0; np < 2; np++) {
                const uint32_t bd =
                    st + 2 * T_A + ((warp_n + np * 16 + bn) * PADK + bk) * 2;
                uint32_t r[4];
                ldsm4(r, bd);
                bh[np * 2 + 0][0] = r[0]; bh[np * 2 + 0][1] = r[2];
                bh[np * 2 + 1][0] = r[1]; bh[np * 2 + 1][1] = r[3];
                ldsm4(r, bd + T_A);
                bl[np * 2 + 0][0] = r[0]; bl[np * 2 + 0][1] = r[2];
                bl[np * 2 + 1][0] = r[1]; bl[np * 2 + 1][1] = r[3];
            }
#pragma unroll
            for (int mi = 0; mi < 4; mi++)
#pragma unroll
                for (int ni = 0; ni < 4; ni++) {
                    mma16816(c[mi][ni], ah[mi], bh[ni]);
                    mma16816(c[mi][ni], ah[mi], bl[ni]);
                    mma16816(c[mi][ni], al[mi], bh[ni]);
                }
        }
        __syncthreads();
    }

    // ---- epilogue: c regs -> global fp32 (+bias) ----
    const int erow = m0 + warp_m + (lane >> 2);
    const int ecol = n0 + warp_n + (lane & 3) * 2;
#pragma unroll
    for (int mi = 0; mi < 4; mi++) {
#pragma unroll
        for (int ni = 0; ni < 4; ni++) {
            const int row = erow + mi * 16;
            const int col = ecol + ni * 8;
            float b0 = 0.0f, b1 = 0.0f;
            if (bias) { b0 = bias[col]; b1 = bias[col + 1]; }
            float2 v0 = make_float2(c[mi][ni][0] + b0, c[mi][ni][1] + b1);
            float2 v1 = make_float2(c[mi][ni][2] + b0, c[mi][ni][3] + b1);
            *(float2*)(C + (size_t)row * N + col)       = v0;
            *(float2*)(C + (size_t)(row + 8) * N + col) = v1;
        }
    }
}

// ---------------------------------------------------------------------------
// Flash attention, fp32 (unchanged, known-good)
// ---------------------------------------------------------------------------
#define LD 68

__global__ __launch_bounds__(256)
void attn_kernel(const float* __restrict__ qkv, float* __restrict__ ctx) {
    const int qt  = blockIdx.x;
    const int h   = blockIdx.y;
    const int b   = blockIdx.z;
    const int tid = threadIdx.x;
    const int tx  = tid & 15;
    const int ty  = tid >> 4;

    extern __shared__ float sm[];
    float* Qs  = sm;
    float* Kts = sm + 64 * LD;
    float* Vs  = sm + 2 * 64 * LD;
    float* Ps  = sm + 3 * 64 * LD;

    const int q0 = qt * 64;
    const size_t base = (size_t)b * SEQ * DIM3 + (size_t)h * HD;

    for (int i = tid; i < 64 * 64; i += 256) {
        int r = i >> 6, d = i & 63;
        Qs[r * LD + d] = qkv[base + (size_t)(q0 + r) * DIM3 + d];
    }

    float m[4], l[4], o[16];
#pragma unroll
    for (int i = 0; i < 4; i++) { m[i] = -1e30f; l[i] = 0.0f; }
#pragma unroll
    for (int i = 0; i < 16; i++) o[i] = 0.0f;

    const float scale = 0.125f;

    for (int kt = 0; kt <= qt; kt++) {
        const int k0 = kt * 64;
        for (int i = tid; i < 64 * 64; i += 256) {
            int r = i >> 6, d = i & 63;
            size_t row = base + (size_t)(k0 + r) * DIM3;
            Kts[d * LD + r] = qkv[row + DIM_OUT + d];
            Vs[r * LD + d]  = qkv[row + 2 * DIM_OUT + d];
        }
        __syncthreads();

        float s[16];
#pragma unroll
        for (int i = 0; i < 16; i++) s[i] = 0.0f;
        for (int d = 0; d < 64; d++) {
            float4 k4 = *(const float4*)&Kts[d * LD + tx * 4];
#pragma unroll
            for (int i = 0; i < 4; i++) {
                float q = Qs[(ty * 4 + i) * LD + d];
                s[i * 4 + 0] = fmaf(q, k4.x, s[i * 4 + 0]);
                s[i * 4 + 1] = fmaf(q, k4.y, s[i * 4 + 1]);
                s[i * 4 + 2] = fmaf(q, k4.z, s[i * 4 + 2]);
                s[i * 4 + 3] = fmaf(q, k4.w, s[i * 4 + 3]);
            }
        }

        const bool diag = (kt == qt);
#pragma unroll
        for (int i = 0; i < 4; i++) {
            int r = ty * 4 + i;
#pragma unroll
            for (int j = 0; j < 4; j++) {
                int cc = tx * 4 + j;
                float v = s[i * 4 + j] * scale;
                if (diag && cc > r) v = -1e30f;
                s[i * 4 + j] = v;
            }
        }

#pragma unroll
        for (int i = 0; i < 4; i++) {
            float mx = fmaxf(fmaxf(s[i*4+0], s[i*4+1]), fmaxf(s[i*4+2], s[i*4+3]));
#pragma unroll
            for (int off = 8; off >= 1; off >>= 1)
                mx = fmaxf(mx, __shfl_xor_sync(0xffffffffu, mx, off));
            float mn    = fmaxf(m[i], mx);
            float alpha = __expf(m[i] - mn);
            float rs = 0.0f;
#pragma unroll
            for (int j = 0; j < 4; j++) {
                float p = __expf(s[i * 4 + j] - mn);
                s[i * 4 + j] = p;
                rs += p;
            }
#pragma unroll
            for (int off = 8; off >= 1; off >>= 1)
                rs += __shfl_xor_sync(0xffffffffu, rs, off);
            l[i] = l[i] * alpha + rs;
            m[i] = mn;
#pragma unroll
            for (int j = 0; j < 4; j++) o[i * 4 + j] *= alpha;
            *(float4*)&Ps[(ty * 4 + i) * LD + tx * 4] = *(float4*)&s[i * 4];
        }
        __syncthreads();

        for (int kv = 0; kv < 64; kv++) {
            float4 v4 = *(const float4*)&Vs[kv * LD + tx * 4];
#pragma unroll
            for (int i = 0; i < 4; i++) {
                float p = Ps[(ty * 4 + i) * LD + kv];
                o[i * 4 + 0] = fmaf(p, v4.x, o[i * 4 + 0]);
                o[i * 4 + 1] = fmaf(p, v4.y, o[i * 4 + 1]);
                o[i * 4 + 2] = fmaf(p, v4.z, o[i * 4 + 2]);
                o[i * 4 + 3] = fmaf(p, v4.w, o[i * 4 + 3]);
            }
        }
        __syncthreads();
    }

#pragma unroll
    for (int i = 0; i < 4; i++) {
        float inv = 1.0f / l[i];
        int r = q0 + ty * 4 + i;
        float4 v;
        v.x = o[i * 4 + 0] * inv;
        v.y = o[i * 4 + 1] * inv;
        v.z = o[i * 4 + 2] * inv;
        v.w = o[i * 4 + 3] * inv;
        *(float4*)&ctx[((size_t)b * SEQ + r) * DIM_OUT + h * HD + tx * 4] = v;
    }
}

// ---------------------------------------------------------------------------
extern "C" void kernel_launch(void* const* d_in, const int* in_sizes, int n_in,
                              void* d_out, int out_size) {
    const float* X     = (const float*)d_in[0];
    const float* W_qkv = (const float*)d_in[1];
    const float* W_out = (const float*)d_in[2];
    const float* b_out = (const float*)d_in[3];
    float* out = (float*)d_out;

    float *qkv, *ctx;
    __nv_bfloat16 *xh, *xl, *ch, *cl, *wqh, *wql, *woh, *wol;
    cudaGetSymbolAddress((void**)&qkv, g_qkv);
    cudaGetSymbolAddress((void**)&ctx, g_ctx);
    cudaGetSymbolAddress((void**)&xh,  g_Xh);
    cudaGetSymbolAddress((void**)&xl,  g_Xl);
    cudaGetSymbolAddress((void**)&ch,  g_Ch);
    cudaGetSymbolAddress((void**)&cl,  g_Cl);
    cudaGetSymbolAddress((void**)&wqh, g_Wqkv_h);
    cudaGetSymbolAddress((void**)&wql, g_Wqkv_l);
    cudaGetSymbolAddress((void**)&woh, g_Wout_h);
    cudaGetSymbolAddress((void**)&wol, g_Wout_l);

    cudaFuncSetAttribute(hmma_gemm_kernel,
                         cudaFuncAttributeMaxDynamicSharedMemorySize, GEMM_SMEM);
    cudaFuncSetAttribute(attn_kernel,
                         cudaFuncAttributeMaxDynamicSharedMemorySize,
                         4 * 64 * LD * (int)sizeof(float));

    // 0) weight transpose+split, X split
    {
        dim3 blk(32, 8);
        transpose_split_kernel<<<dim3(DIM3 / 32, DIM_IN / 32), blk>>>(
            W_qkv, DIM_IN, DIM3, wqh, wql);
        transpose_split_kernel<<<dim3(DIM_OUT / 32, DIM_OUT / 32), blk>>>(
            W_out, DIM_OUT, DIM_OUT, woh, wol);
        const int n4 = NTOK * DIM_IN / 4;
        split_rows_kernel<<<(n4 + 255) / 256, 256>>>(
            (const float4*)X, n4, (uint2*)xh, (uint2*)xl);
    }

    // 1) QKV projection (HMMA): [8192,1024] @ [1024,3072]
    hmma_gemm_kernel<<<dim3(DIM3 / BN, NTOK / BM), 256, GEMM_SMEM>>>(
        NTOK, DIM3, DIM_IN, xh, xl, wqh, wql, qkv, nullptr);

    // 2) causal flash attention (fp32)
    attn_kernel<<<dim3(SEQ / 64, NHEADS, B_DIM), 256,
                  4 * 64 * LD * sizeof(float)>>>(qkv, ctx);

    // 3) split ctx, out projection + bias (HMMA)
    {
        const int n4 = NTOK * DIM_OUT / 4;
        split_rows_kernel<<<(n4 + 255) / 256, 256>>>(
            (const float4*)ctx, n4, (uint2*)ch, (uint2*)cl);
    }
    hmma_gemm_kernel<<<dim3(DIM_OUT / BN, NTOK / BM), 256, GEMM_SMEM>>>(
        NTOK, DIM_OUT, DIM_OUT, ch, cl, woh, wol, out, b_out);
}

// round 8
// speedup vs baseline: 2.2978x; 1.5118x over previous
#include <cuda_runtime.h>
#include <cuda_bf16.h>
#include <cstdint>
#include <math.h>

#define B_DIM   4
#define SEQ     2048
#define DIM_IN  1024
#define DIM_OUT 1024
#define DIM3    3072
#define NHEADS  16
#define HD      64
#define NTOK    (B_DIM * SEQ)        // 8192

// ---------------------------------------------------------------------------
// Scratch (__device__ globals: allocation-free rule)
// ---------------------------------------------------------------------------
__device__ float g_qkv[(size_t)NTOK * DIM3];
__device__ float g_ctx[(size_t)NTOK * DIM_OUT];
__device__ __nv_bfloat16 g_Xh[(size_t)NTOK * DIM_IN];
__device__ __nv_bfloat16 g_Xl[(size_t)NTOK * DIM_IN];
__device__ __nv_bfloat16 g_Ch[(size_t)NTOK * DIM_OUT];
__device__ __nv_bfloat16 g_Cl[(size_t)NTOK * DIM_OUT];
__device__ __nv_bfloat16 g_Wqkv_h[(size_t)DIM3 * DIM_IN];    // [N][K]
__device__ __nv_bfloat16 g_Wqkv_l[(size_t)DIM3 * DIM_IN];
__device__ __nv_bfloat16 g_Wout_h[(size_t)DIM_OUT * DIM_OUT];
__device__ __nv_bfloat16 g_Wout_l[(size_t)DIM_OUT * DIM_OUT];

// ---------------------------------------------------------------------------
// PTX helpers (compute_103-safe: mma.sync / ldmatrix / cp.async only)
// ---------------------------------------------------------------------------
__device__ __forceinline__ uint32_t smem_u32(const void* p) {
    uint32_t a;
    asm("{ .reg .u64 t; cvta.to.shared.u64 t, %1; cvt.u32.u64 %0, t; }"
        : "=r"(a) : "l"(p));
    return a;
}

__device__ __forceinline__ void cp16(uint32_t dst, const void* src) {
    asm volatile("cp.async.cg.shared.global [%0], [%1], 16;"
                 :: "r"(dst), "l"(src));
}
#define CP_COMMIT() asm volatile("cp.async.commit_group;")
#define CP_WAIT1()  asm volatile("cp.async.wait_group 1;")

__device__ __forceinline__ void ldsm4(uint32_t* r, uint32_t addr) {
    asm volatile("ldmatrix.sync.aligned.m8n8.x4.shared.b16 {%0,%1,%2,%3}, [%4];"
                 : "=r"(r[0]), "=r"(r[1]), "=r"(r[2]), "=r"(r[3]) : "r"(addr));
}

__device__ __forceinline__ void mma16816(float* c, const uint32_t* a, const uint32_t* b) {
    asm volatile(
        "mma.sync.aligned.m16n8k16.row.col.f32.bf16.bf16.f32 "
        "{%0,%1,%2,%3}, {%4,%5,%6,%7}, {%8,%9}, {%0,%1,%2,%3};"
        : "+f"(c[0]), "+f"(c[1]), "+f"(c[2]), "+f"(c[3])
        : "r"(a[0]), "r"(a[1]), "r"(a[2]), "r"(a[3]), "r"(b[0]), "r"(b[1]));
}

__device__ __forceinline__ uint32_t pack_bf2(__nv_bfloat16 x, __nv_bfloat16 y) {
    __nv_bfloat162 p = __halves2bfloat162(x, y);
    return *(uint32_t*)&p;
}

__device__ __forceinline__ void split_pack(float x, float y, uint32_t& hi, uint32_t& lo) {
    __nv_bfloat16 hx = __float2bfloat16(x);
    __nv_bfloat16 hy = __float2bfloat16(y);
    __nv_bfloat16 lx = __float2bfloat16(x - __bfloat162float(hx));
    __nv_bfloat16 ly = __float2bfloat16(y - __bfloat162float(hy));
    hi = pack_bf2(hx, hy);
    lo = pack_bf2(lx, ly);
}

// ---------------------------------------------------------------------------
// Split fp32 -> bf16 hi/lo (row-major)
// ---------------------------------------------------------------------------
__global__ __launch_bounds__(256)
void split_rows_kernel(const float4* __restrict__ A, int n4,
                       uint2* __restrict__ H, uint2* __restrict__ L) {
    int i = blockIdx.x * 256 + threadIdx.x;
    if (i >= n4) return;
    float4 v = A[i];
    __nv_bfloat16 h0 = __float2bfloat16(v.x), h1 = __float2bfloat16(v.y);
    __nv_bfloat16 h2 = __float2bfloat16(v.z), h3 = __float2bfloat16(v.w);
    __nv_bfloat16 l0 = __float2bfloat16(v.x - __bfloat162float(h0));
    __nv_bfloat16 l1 = __float2bfloat16(v.y - __bfloat162float(h1));
    __nv_bfloat16 l2 = __float2bfloat16(v.z - __bfloat162float(h2));
    __nv_bfloat16 l3 = __float2bfloat16(v.w - __bfloat162float(h3));
    uint2 hh, ll;
    hh.x = pack_bf2(h0, h1); hh.y = pack_bf2(h2, h3);
    ll.x = pack_bf2(l0, l1); ll.y = pack_bf2(l2, l3);
    H[i] = hh;
    L[i] = ll;
}

// ---------------------------------------------------------------------------
// Transpose + split: W [K][N] fp32 -> Th/Tl [N][K] bf16
// ---------------------------------------------------------------------------
__global__ void transpose_split_kernel(const float* __restrict__ W, int K, int N,
                                       __nv_bfloat16* __restrict__ Th,
                                       __nv_bfloat16* __restrict__ Tl) {
    __shared__ float t[32][33];
    const int n0 = blockIdx.x * 32;
    const int k0 = blockIdx.y * 32;
    const int tx = threadIdx.x, ty = threadIdx.y;   // 32 x 8
#pragma unroll
    for (int i = 0; i < 32; i += 8)
        t[ty + i][tx] = W[(size_t)(k0 + ty + i) * N + n0 + tx];
    __syncthreads();
#pragma unroll
    for (int i = 0; i < 32; i += 8) {
        float v = t[tx][ty + i];
        __nv_bfloat16 h = __float2bfloat16(v);
        __nv_bfloat16 l = __float2bfloat16(v - __bfloat162float(h));
        Th[(size_t)(n0 + ty + i) * K + k0 + tx] = h;
        Tl[(size_t)(n0 + ty + i) * K + k0 + tx] = l;
    }
}

// ---------------------------------------------------------------------------
// HMMA GEMM (unchanged from R6 except min-blocks 2)
// ---------------------------------------------------------------------------
#define BM 128
#define BN 128
#define BK 32
#define PADK 40
#define T_A  (BM * PADK * 2)
#define STAGE_B (4 * T_A)
#define GEMM_SMEM (2 * STAGE_B)

__global__ __launch_bounds__(256, 2)
void hmma_gemm_kernel(int M, int N, int K,
                      const __nv_bfloat16* __restrict__ Ah,
                      const __nv_bfloat16* __restrict__ Al,
                      const __nv_bfloat16* __restrict__ Bh,
                      const __nv_bfloat16* __restrict__ Bl,
                      float* __restrict__ C,
                      const float* __restrict__ bias) {
    extern __shared__ char smem[];
    const uint32_t sbase = smem_u32(smem);
    const int tid  = threadIdx.x;
    const int lane = tid & 31;
    const int wid  = tid >> 5;
    const int m0 = blockIdx.y * BM;
    const int n0 = blockIdx.x * BN;
    const int warp_m = (wid & 1) * 64;
    const int warp_n = (wid >> 1) * 32;

    float c[4][4][4];
#pragma unroll
    for (int i = 0; i < 4; i++)
#pragma unroll
        for (int j = 0; j < 4; j++)
#pragma unroll
            for (int k = 0; k < 4; k++) c[i][j][k] = 0.0f;

    auto load_stage = [&](int s, int kb) {
        const uint32_t st = sbase + s * STAGE_B;
#pragma unroll
        for (int r = 0; r < 2; r++) {
            const int i   = tid + r * 256;
            const int row = i >> 2;
            const int seg = i & 3;
            const uint32_t off = row * (PADK * 2) + seg * 16;
            const size_t ga = (size_t)(m0 + row) * K + kb + seg * 8;
            const size_t gb = (size_t)(n0 + row) * K + kb + seg * 8;
            cp16(st + off,             Ah + ga);
            cp16(st + T_A + off,       Al + ga);
            cp16(st + 2 * T_A + off,   Bh + gb);
            cp16(st + 3 * T_A + off,   Bl + gb);
        }
    };

    const int NKB = K / BK;
    load_stage(0, 0);
    CP_COMMIT();

    for (int kb = 0; kb < NKB; kb++) {
        if (kb + 1 < NKB) load_stage((kb + 1) & 1, (kb + 1) * BK);
        CP_COMMIT();
        CP_WAIT1();
        __syncthreads();

        const uint32_t st = sbase + (kb & 1) * STAGE_B;
#pragma unroll
        for (int ks = 0; ks < 2; ks++) {
            uint32_t ah[4][4], al[4][4], bh[4][2], bl[4][2];
            const int arow = warp_m + (lane & 15);
            const int acol = ks * 16 + (lane >> 4) * 8;
#pragma unroll
            for (int mi = 0; mi < 4; mi++) {
                const uint32_t ad = st + ((arow + mi * 16) * PADK + acol) * 2;
                ldsm4(ah[mi], ad);
                ldsm4(al[mi], ad + T_A);
            }
            const int bn = ((lane >> 3) & 1) * 8 + (lane & 7);
            const int bk = ks * 16 + (lane >> 4) * 8;
#pragma unroll
            for (int np = 0; np < 2; np++) {
                const uint32_t bd =
                    st + 2 * T_A + ((warp_n + np * 16 + bn) * PADK + bk) * 2;
                uint32_t r[4];
                ldsm4(r, bd);
                bh[np * 2 + 0][0] = r[0]; bh[np * 2 + 0][1] = r[2];
                bh[np * 2 + 1][0] = r[1]; bh[np * 2 + 1][1] = r[3];
                ldsm4(r, bd + T_A);
                bl[np * 2 + 0][0] = r[0]; bl[np * 2 + 0][1] = r[2];
                bl[np * 2 + 1][0] = r[1]; bl[np * 2 + 1][1] = r[3];
            }
#pragma unroll
            for (int mi = 0; mi < 4; mi++)
#pragma unroll
                for (int ni = 0; ni < 4; ni++) {
                    mma16816(c[mi][ni], ah[mi], bh[ni]);
                    mma16816(c[mi][ni], ah[mi], bl[ni]);
                    mma16816(c[mi][ni], al[mi], bh[ni]);
                }
        }
        __syncthreads();
    }

    const int erow = m0 + warp_m + (lane >> 2);
    const int ecol = n0 + warp_n + (lane & 3) * 2;
#pragma unroll
    for (int mi = 0; mi < 4; mi++) {
#pragma unroll
        for (int ni = 0; ni < 4; ni++) {
            const int row = erow + mi * 16;
            const int col = ecol + ni * 8;
            float b0 = 0.0f, b1 = 0.0f;
            if (bias) { b0 = bias[col]; b1 = bias[col + 1]; }
            float2 v0 = make_float2(c[mi][ni][0] + b0, c[mi][ni][1] + b1);
            float2 v1 = make_float2(c[mi][ni][2] + b0, c[mi][ni][3] + b1);
            *(float2*)(C + (size_t)row * N + col)       = v0;
            *(float2*)(C + (size_t)(row + 8) * N + col) = v1;
        }
    }
}

// ---------------------------------------------------------------------------
// HMMA flash attention with 3-term bf16 split.
// Q-tile 128, K-tile 64, 8 warps: warp w owns q-rows [w*16, w*16+16).
// ---------------------------------------------------------------------------
#define QT 128
#define KT 64
#define APAD 72                       // halves per row: 144 B, ldsm conflict-free
#define ATT_SMEM ((2 * QT + 4 * KT) * APAD * 2)   // 73728 B

__global__ __launch_bounds__(256)
void attn_hmma_kernel(const float* __restrict__ qkv, float* __restrict__ ctx) {
    extern __shared__ char smc[];
    __nv_bfloat16* Qh  = (__nv_bfloat16*)smc;
    __nv_bfloat16* Ql  = Qh  + QT * APAD;
    __nv_bfloat16* Kh  = Ql  + QT * APAD;
    __nv_bfloat16* Kl  = Kh  + KT * APAD;
    __nv_bfloat16* Vth = Kl  + KT * APAD;     // [d][kv]
    __nv_bfloat16* Vtl = Vth + KT * APAD;

    const int qt = blockIdx.x, h = blockIdx.y, b = blockIdx.z;
    const int tid = threadIdx.x, lane = tid & 31, w = tid >> 5;
    const int q0 = qt * QT;
    const size_t base = (size_t)b * SEQ * DIM3 + (size_t)h * HD;

    const uint32_t sQh = smem_u32(Qh), sQl = smem_u32(Ql);
    const uint32_t sKh = smem_u32(Kh), sKl = smem_u32(Kl);
    const uint32_t sVh = smem_u32(Vth), sVl = smem_u32(Vtl);

    // load Q (scale 1/8 folded in), split hi/lo
    for (int i = tid; i < QT * HD; i += 256) {
        const int r = i >> 6, d = i & 63;
        float v = qkv[base + (size_t)(q0 + r) * DIM3 + d] * 0.125f;
        __nv_bfloat16 hi = __float2bfloat16(v);
        Qh[r * APAD + d] = hi;
        Ql[r * APAD + d] = __float2bfloat16(v - __bfloat162float(hi));
    }

    float o[8][4];
#pragma unroll
    for (int t = 0; t < 8; t++)
#pragma unroll
        for (int j = 0; j < 4; j++) o[t][j] = 0.0f;
    float mrow[2] = {-1e30f, -1e30f};
    float lrow[2] = {0.0f, 0.0f};

    const int nkt = (q0 + QT) / KT;
    for (int kt = 0; kt < nkt; kt++) {
        const int k0 = kt * KT;
        __syncthreads();   // previous-tile reads done before overwrite
        for (int i = tid; i < KT * HD; i += 256) {
            const int r = i >> 6, d = i & 63;
            const size_t row = base + (size_t)(k0 + r) * DIM3;
            float kv = qkv[row + DIM_OUT + d];
            __nv_bfloat16 khi = __float2bfloat16(kv);
            Kh[r * APAD + d] = khi;
            Kl[r * APAD + d] = __float2bfloat16(kv - __bfloat162float(khi));
            float vv = qkv[row + 2 * DIM_OUT + d];
            __nv_bfloat16 vhi = __float2bfloat16(vv);
            Vth[d * APAD + r] = vhi;
            Vtl[d * APAD + r] = __float2bfloat16(vv - __bfloat162float(vhi));
        }
        __syncthreads();

        // ---- S = Q @ K^T (3-term split), warp tile 16 x 64 ----
        float sc[8][4];
#pragma unroll
        for (int t = 0; t < 8; t++)
#pragma unroll
            for (int j = 0; j < 4; j++) sc[t][j] = 0.0f;

#pragma unroll
        for (int ks = 0; ks < 4; ks++) {
            const int arow = w * 16 + (lane & 15);
            const int acol = ks * 16 + (lane >> 4) * 8;
            uint32_t ah[4], al[4];
            ldsm4(ah, sQh + (arow * APAD + acol) * 2);
            ldsm4(al, sQl + (arow * APAD + acol) * 2);
            uint32_t bh[8][2], bl[8][2];
            const int bn = ((lane >> 3) & 1) * 8 + (lane & 7);
#pragma unroll
            for (int np = 0; np < 4; np++) {
                const uint32_t off = ((np * 16 + bn) * APAD + acol) * 2;
                uint32_t r[4];
                ldsm4(r, sKh + off);
                bh[np * 2 + 0][0] = r[0]; bh[np * 2 + 0][1] = r[2];
                bh[np * 2 + 1][0] = r[1]; bh[np * 2 + 1][1] = r[3];
                ldsm4(r, sKl + off);
                bl[np * 2 + 0][0] = r[0]; bl[np * 2 + 0][1] = r[2];
                bl[np * 2 + 1][0] = r[1]; bl[np * 2 + 1][1] = r[3];
            }
#pragma unroll
            for (int t = 0; t < 8; t++) {
                mma16816(sc[t], ah, bh[t]);
                mma16816(sc[t], ah, bl[t]);
                mma16816(sc[t], al, bh[t]);
            }
        }

        // ---- causal mask (only near-diagonal tiles) ----
        const int row0 = q0 + w * 16 + (lane >> 2);
        if (k0 + KT - 1 > q0 + w * 16) {
#pragma unroll
            for (int t = 0; t < 8; t++) {
                const int col = k0 + t * 8 + (lane & 3) * 2;
                if (col     > row0)     sc[t][0] = -1e30f;
                if (col + 1 > row0)     sc[t][1] = -1e30f;
                if (col     > row0 + 8) sc[t][2] = -1e30f;
                if (col + 1 > row0 + 8) sc[t][3] = -1e30f;
            }
        }

        // ---- online softmax (rows live in lane quads) ----
#pragma unroll
        for (int rh = 0; rh < 2; rh++) {
            const int i0 = rh * 2;
            float mx = -1e30f;
#pragma unroll
            for (int t = 0; t < 8; t++)
                mx = fmaxf(mx, fmaxf(sc[t][i0], sc[t][i0 + 1]));
            mx = fmaxf(mx, __shfl_xor_sync(0xffffffffu, mx, 1));
            mx = fmaxf(mx, __shfl_xor_sync(0xffffffffu, mx, 2));
            const float mn = fmaxf(mrow[rh], mx);
            const float alpha = __expf(mrow[rh] - mn);
            float rs = 0.0f;
#pragma unroll
            for (int t = 0; t < 8; t++) {
                const float p0 = __expf(sc[t][i0] - mn);
                const float p1 = __expf(sc[t][i0 + 1] - mn);
                sc[t][i0] = p0; sc[t][i0 + 1] = p1;
                rs += p0 + p1;
            }
            rs += __shfl_xor_sync(0xffffffffu, rs, 1);
            rs += __shfl_xor_sync(0xffffffffu, rs, 2);
            lrow[rh] = lrow[rh] * alpha + rs;
            mrow[rh] = mn;
#pragma unroll
            for (int t = 0; t < 8; t++) { o[t][i0] *= alpha; o[t][i0 + 1] *= alpha; }
        }

        // ---- O += P @ V (3-term split); P from regs, V^T from smem ----
#pragma unroll
        for (int ks = 0; ks < 4; ks++) {
            uint32_t ph[4], pl[4];
            split_pack(sc[2 * ks][0],     sc[2 * ks][1],     ph[0], pl[0]);
            split_pack(sc[2 * ks][2],     sc[2 * ks][3],     ph[1], pl[1]);
            split_pack(sc[2 * ks + 1][0], sc[2 * ks + 1][1], ph[2], pl[2]);
            split_pack(sc[2 * ks + 1][2], sc[2 * ks + 1][3], ph[3], pl[3]);

            uint32_t vh[8][2], vl[8][2];
            const int bn = ((lane >> 3) & 1) * 8 + (lane & 7);
            const int bk = ks * 16 + (lane >> 4) * 8;
#pragma unroll
            for (int np = 0; np < 4; np++) {
                const uint32_t off = ((np * 16 + bn) * APAD + bk) * 2;
                uint32_t r[4];
                ldsm4(r, sVh + off);
                vh[np * 2 + 0][0] = r[0]; vh[np * 2 + 0][1] = r[2];
                vh[np * 2 + 1][0] = r[1]; vh[np * 2 + 1][1] = r[3];
                ldsm4(r, sVl + off);
                vl[np * 2 + 0][0] = r[0]; vl[np * 2 + 0][1] = r[2];
                vl[np * 2 + 1][0] = r[1]; vl[np * 2 + 1][1] = r[3];
            }
#pragma unroll
            for (int t = 0; t < 8; t++) {
                mma16816(o[t], ph, vh[t]);
                mma16816(o[t], ph, vl[t]);
                mma16816(o[t], pl, vh[t]);
            }
        }
    }

    // ---- normalize, write ctx[b, row, h*64 + d] ----
    const float inv0 = 1.0f / lrow[0];
    const float inv1 = 1.0f / lrow[1];
    const int row0 = q0 + w * 16 + (lane >> 2);
#pragma unroll
    for (int t = 0; t < 8; t++) {
        const int col = h * HD + t * 8 + (lane & 3) * 2;
        *(float2*)&ctx[((size_t)b * SEQ + row0) * DIM_OUT + col] =
            make_float2(o[t][0] * inv0, o[t][1] * inv0);
        *(float2*)&ctx[((size_t)b * SEQ + row0 + 8) * DIM_OUT + col] =
            make_float2(o[t][2] * inv1, o[t][3] * inv1);
    }
}

// ---------------------------------------------------------------------------
extern "C" void kernel_launch(void* const* d_in, const int* in_sizes, int n_in,
                              void* d_out, int out_size) {
    const float* X     = (const float*)d_in[0];
    const float* W_qkv = (const float*)d_in[1];
    const float* W_out = (const float*)d_in[2];
    const float* b_out = (const float*)d_in[3];
    float* out = (float*)d_out;

    float *qkv, *ctx;
    __nv_bfloat16 *xh, *xl, *ch, *cl, *wqh, *wql, *woh, *wol;
    cudaGetSymbolAddress((void**)&qkv, g_qkv);
    cudaGetSymbolAddress((void**)&ctx, g_ctx);
    cudaGetSymbolAddress((void**)&xh,  g_Xh);
    cudaGetSymbolAddress((void**)&xl,  g_Xl);
    cudaGetSymbolAddress((void**)&ch,  g_Ch);
    cudaGetSymbolAddress((void**)&cl,  g_Cl);
    cudaGetSymbolAddress((void**)&wqh, g_Wqkv_h);
    cudaGetSymbolAddress((void**)&wql, g_Wqkv_l);
    cudaGetSymbolAddress((void**)&woh, g_Wout_h);
    cudaGetSymbolAddress((void**)&wol, g_Wout_l);

    cudaFuncSetAttribute(hmma_gemm_kernel,
                         cudaFuncAttributeMaxDynamicSharedMemorySize, GEMM_SMEM);
    cudaFuncSetAttribute(attn_hmma_kernel,
                         cudaFuncAttributeMaxDynamicSharedMemorySize, ATT_SMEM);

    // 0) weight transpose+split, X split
    {
        dim3 blk(32, 8);
        transpose_split_kernel<<<dim3(DIM3 / 32, DIM_IN / 32), blk>>>(
            W_qkv, DIM_IN, DIM3, wqh, wql);
        transpose_split_kernel<<<dim3(DIM_OUT / 32, DIM_OUT / 32), blk>>>(
            W_out, DIM_OUT, DIM_OUT, woh, wol);
        const int n4 = NTOK * DIM_IN / 4;
        split_rows_kernel<<<(n4 + 255) / 256, 256>>>(
            (const float4*)X, n4, (uint2*)xh, (uint2*)xl);
    }

    // 1) QKV projection (HMMA)
    hmma_gemm_kernel<<<dim3(DIM3 / BN, NTOK / BM), 256, GEMM_SMEM>>>(
        NTOK, DIM3, DIM_IN, xh, xl, wqh, wql, qkv, nullptr);

    // 2) causal flash attention (HMMA split)
    attn_hmma_kernel<<<dim3(SEQ / QT, NHEADS, B_DIM), 256, ATT_SMEM>>>(qkv, ctx);

    // 3) split ctx, out projection + bias (HMMA)
    {
        const int n4 = NTOK * DIM_OUT / 4;
        split_rows_kernel<<<(n4 + 255) / 256, 256>>>(
            (const float4*)ctx, n4, (uint2*)ch, (uint2*)cl);
    }
    hmma_gemm_kernel<<<dim3(DIM_OUT / BN, NTOK / BM), 256, GEMM_SMEM>>>(
        NTOK, DIM_OUT, DIM_OUT, ch, cl, woh, wol, out, b_out);
}

// round 13
// speedup vs baseline: 2.5230x; 1.0980x over previous
#include <cuda_runtime.h>
#include <cuda_bf16.h>
#include <cstdint>
#include <math.h>

#define B_DIM   4
#define SEQ     2048
#define DIM_IN  1024
#define DIM_OUT 1024
#define DIM3    3072
#define NHEADS  16
#define HD      64
#define NTOK    (B_DIM * SEQ)        // 8192

// ---------------------------------------------------------------------------
// Scratch (__device__ globals: allocation-free rule)
// ---------------------------------------------------------------------------
__device__ __nv_bfloat16 g_qkvh[(size_t)NTOK * DIM3];        // hi split of qkv
__device__ __nv_bfloat16 g_qkvl[(size_t)NTOK * DIM3];        // lo split of qkv
__device__ __nv_bfloat16 g_Xh[(size_t)NTOK * DIM_IN];
__device__ __nv_bfloat16 g_Xl[(size_t)NTOK * DIM_IN];
__device__ __nv_bfloat16 g_Ch[(size_t)NTOK * DIM_OUT];       // ctx hi
__device__ __nv_bfloat16 g_Cl[(size_t)NTOK * DIM_OUT];       // ctx lo
__device__ __nv_bfloat16 g_Wqkv_h[(size_t)DIM3 * DIM_IN];    // [N][K]
__device__ __nv_bfloat16 g_Wqkv_l[(size_t)DIM3 * DIM_IN];
__device__ __nv_bfloat16 g_Wout_h[(size_t)DIM_OUT * DIM_OUT];
__device__ __nv_bfloat16 g_Wout_l[(size_t)DIM_OUT * DIM_OUT];

// ---------------------------------------------------------------------------
// PTX helpers (compute_103-safe: mma.sync / ldmatrix / cp.async only)
// ---------------------------------------------------------------------------
__device__ __forceinline__ uint32_t smem_u32(const void* p) {
    uint32_t a;
    asm("{ .reg .u64 t; cvta.to.shared.u64 t, %1; cvt.u32.u64 %0, t; }"
        : "=r"(a) : "l"(p));
    return a;
}

__device__ __forceinline__ void cp16(uint32_t dst, const void* src) {
    asm volatile("cp.async.cg.shared.global [%0], [%1], 16;"
                 :: "r"(dst), "l"(src));
}
#define CP_COMMIT() asm volatile("cp.async.commit_group;")
#define CP_WAIT1()  asm volatile("cp.async.wait_group 1;")

__device__ __forceinline__ void ldsm4(uint32_t* r, uint32_t addr) {
    asm volatile("ldmatrix.sync.aligned.m8n8.x4.shared.b16 {%0,%1,%2,%3}, [%4];"
                 : "=r"(r[0]), "=r"(r[1]), "=r"(r[2]), "=r"(r[3]) : "r"(addr));
}

__device__ __forceinline__ void ldsm4t(uint32_t* r, uint32_t addr) {
    asm volatile("ldmatrix.sync.aligned.m8n8.x4.trans.shared.b16 {%0,%1,%2,%3}, [%4];"
                 : "=r"(r[0]), "=r"(r[1]), "=r"(r[2]), "=r"(r[3]) : "r"(addr));
}

__device__ __forceinline__ void mma16816(float* c, const uint32_t* a, const uint32_t* b) {
    asm volatile(
        "mma.sync.aligned.m16n8k16.row.col.f32.bf16.bf16.f32 "
        "{%0,%1,%2,%3}, {%4,%5,%6,%7}, {%8,%9}, {%0,%1,%2,%3};"
        : "+f"(c[0]), "+f"(c[1]), "+f"(c[2]), "+f"(c[3])
        : "r"(a[0]), "r"(a[1]), "r"(a[2]), "r"(a[3]), "r"(b[0]), "r"(b[1]));
}

__device__ __forceinline__ uint32_t pack_bf2(__nv_bfloat16 x, __nv_bfloat16 y) {
    __nv_bfloat162 p = __halves2bfloat162(x, y);
    return *(uint32_t*)&p;
}

__device__ __forceinline__ void split_pack(float x, float y, uint32_t& hi, uint32_t& lo) {
    __nv_bfloat16 hx = __float2bfloat16(x);
    __nv_bfloat16 hy = __float2bfloat16(y);
    __nv_bfloat16 lx = __float2bfloat16(x - __bfloat162float(hx));
    __nv_bfloat16 ly = __float2bfloat16(y - __bfloat162float(hy));
    hi = pack_bf2(hx, hy);
    lo = pack_bf2(lx, ly);
}

// ---------------------------------------------------------------------------
// Split fp32 -> bf16 hi/lo (row-major)
// ---------------------------------------------------------------------------
__global__ __launch_bounds__(256)
void split_rows_kernel(const float4* __restrict__ A, int n4,
                       uint2* __restrict__ H, uint2* __restrict__ L) {
    int i = blockIdx.x * 256 + threadIdx.x;
    if (i >= n4) return;
    float4 v = A[i];
    __nv_bfloat16 h0 = __float2bfloat16(v.x), h1 = __float2bfloat16(v.y);
    __nv_bfloat16 h2 = __float2bfloat16(v.z), h3 = __float2bfloat16(v.w);
    __nv_bfloat16 l0 = __float2bfloat16(v.x - __bfloat162float(h0));
    __nv_bfloat16 l1 = __float2bfloat16(v.y - __bfloat162float(h1));
    __nv_bfloat16 l2 = __float2bfloat16(v.z - __bfloat162float(h2));
    __nv_bfloat16 l3 = __float2bfloat16(v.w - __bfloat162float(h3));
    uint2 hh, ll;
    hh.x = pack_bf2(h0, h1); hh.y = pack_bf2(h2, h3);
    ll.x = pack_bf2(l0, l1); ll.y = pack_bf2(l2, l3);
    H[i] = hh;
    L[i] = ll;
}

// ---------------------------------------------------------------------------
// Transpose + split: W [K][N] fp32 -> Th/Tl [N][K] bf16
// ---------------------------------------------------------------------------
__global__ void transpose_split_kernel(const float* __restrict__ W, int K, int N,
                                       __nv_bfloat16* __restrict__ Th,
                                       __nv_bfloat16* __restrict__ Tl) {
    __shared__ float t[32][33];
    const int n0 = blockIdx.x * 32;
    const int k0 = blockIdx.y * 32;
    const int tx = threadIdx.x, ty = threadIdx.y;   // 32 x 8
#pragma unroll
    for (int i = 0; i < 32; i += 8)
        t[ty + i][tx] = W[(size_t)(k0 + ty + i) * N + n0 + tx];
    __syncthreads();
#pragma unroll
    for (int i = 0; i < 32; i += 8) {
        float v = t[tx][ty + i];
        __nv_bfloat16 h = __float2bfloat16(v);
        __nv_bfloat16 l = __float2bfloat16(v - __bfloat162float(h));
        Th[(size_t)(n0 + ty + i) * K + k0 + tx] = h;
        Tl[(size_t)(n0 + ty + i) * K + k0 + tx] = l;
    }
}

// ---------------------------------------------------------------------------
// HMMA GEMM.  Epilogue: either fp32(+bias) to C, or bf16 hi/lo split to Ch/Cl
// (with columns < scale_cols multiplied by 0.125 first — exact pow2).
// ---------------------------------------------------------------------------
#define BM 128
#define BN 128
#define BK 32
#define PADK 40
#define T_A  (BM * PADK * 2)
#define STAGE_B (4 * T_A)
#define GEMM_SMEM (2 * STAGE_B)

__global__ __launch_bounds__(256, 2)
void hmma_gemm_kernel(int M, int N, int K,
                      const __nv_bfloat16* __restrict__ Ah,
                      const __nv_bfloat16* __restrict__ Al,
                      const __nv_bfloat16* __restrict__ Bh,
                      const __nv_bfloat16* __restrict__ Bl,
                      float* __restrict__ C,
                      const float* __restrict__ bias,
                      __nv_bfloat16* __restrict__ Ch,
                      __nv_bfloat16* __restrict__ Cl,
                      int scale_cols) {
    extern __shared__ char smem[];
    const uint32_t sbase = smem_u32(smem);
    const int tid  = threadIdx.x;
    const int lane = tid & 31;
    const int wid  = tid >> 5;
    const int m0 = blockIdx.y * BM;
    const int n0 = blockIdx.x * BN;
    const int warp_m = (wid & 1) * 64;
    const int warp_n = (wid >> 1) * 32;

    float c[4][4][4];
#pragma unroll
    for (int i = 0; i < 4; i++)
#pragma unroll
        for (int j = 0; j < 4; j++)
#pragma unroll
            for (int k = 0; k < 4; k++) c[i][j][k] = 0.0f;

    auto load_stage = [&](int s, int kb) {
        const uint32_t st = sbase + s * STAGE_B;
#pragma unroll
        for (int r = 0; r < 2; r++) {
            const int i   = tid + r * 256;
            const int row = i >> 2;
            const int seg = i & 3;
            const uint32_t off = row * (PADK * 2) + seg * 16;
            const size_t ga = (size_t)(m0 + row) * K + kb + seg * 8;
            const size_t gb = (size_t)(n0 + row) * K + kb + seg * 8;
            cp16(st + off,             Ah + ga);
            cp16(st + T_A + off,       Al + ga);
            cp16(st + 2 * T_A + off,   Bh + gb);
            cp16(st + 3 * T_A + off,   Bl + gb);
        }
    };

    const int NKB = K / BK;
    load_stage(0, 0);
    CP_COMMIT();

    for (int kb = 0; kb < NKB; kb++) {
        if (kb + 1 < NKB) load_stage((kb + 1) & 1, (kb + 1) * BK);
        CP_COMMIT();
        CP_WAIT1();
        __syncthreads();

        const uint32_t st = sbase + (kb & 1) * STAGE_B;
#pragma unroll
        for (int ks = 0; ks < 2; ks++) {
            uint32_t ah[4][4], al[4][4], bh[4][2], bl[4][2];
            const int arow = warp_m + (lane & 15);
            const int acol = ks * 16 + (lane >> 4) * 8;
#pragma unroll
            for (int mi = 0; mi < 4; mi++) {
                const uint32_t ad = st + ((arow + mi * 16) * PADK + acol) * 2;
                ldsm4(ah[mi], ad);
                ldsm4(al[mi], ad + T_A);
            }
            const int bn = ((lane >> 3) & 1) * 8 + (lane & 7);
            const int bk = ks * 16 + (lane >> 4) * 8;
#pragma unroll
            for (int np = 0; np < 2; np++) {
                const uint32_t bd =
                    st + 2 * T_A + ((warp_n + np * 16 + bn) * PADK + bk) * 2;
                uint32_t r[4];
                ldsm4(r, bd);
                bh[np * 2 + 0][0] = r[0]; bh[np * 2 + 0][1] = r[2];
                bh[np * 2 + 1][0] = r[1]; bh[np * 2 + 1][1] = r[3];
                ldsm4(r, bd + T_A);
                bl[np * 2 + 0][0] = r[0]; bl[np * 2 + 0][1] = r[2];
                bl[np * 2 + 1][0] = r[1]; bl[np * 2 + 1][1] = r[3];
            }
#pragma unroll
            for (int mi = 0; mi < 4; mi++)
#pragma unroll
                for (int ni = 0; ni < 4; ni++) {
                    mma16816(c[mi][ni], ah[mi], bh[ni]);
                    mma16816(c[mi][ni], ah[mi], bl[ni]);
                    mma16816(c[mi][ni], al[mi], bh[ni]);
                }
        }
        __syncthreads();
    }

    const int erow = m0 + warp_m + (lane >> 2);
    const int ecol = n0 + warp_n + (lane & 3) * 2;
#pragma unroll
    for (int mi = 0; mi < 4; mi++) {
#pragma unroll
        for (int ni = 0; ni < 4; ni++) {
            const int row = erow + mi * 16;
            const int col = ecol + ni * 8;
            if (Ch) {
                const float s = (col < scale_cols) ? 0.125f : 1.0f;
                uint32_t hi, lo;
                split_pack(c[mi][ni][0] * s, c[mi][ni][1] * s, hi, lo);
                *(uint32_t*)(Ch + (size_t)row * N + col) = hi;
                *(uint32_t*)(Cl + (size_t)row * N + col) = lo;
                split_pack(c[mi][ni][2] * s, c[mi][ni][3] * s, hi, lo);
                *(uint32_t*)(Ch + (size_t)(row + 8) * N + col) = hi;
                *(uint32_t*)(Cl + (size_t)(row + 8) * N + col) = lo;
            } else {
                float b0 = 0.0f, b1 = 0.0f;
                if (bias) { b0 = bias[col]; b1 = bias[col + 1]; }
                float2 v0 = make_float2(c[mi][ni][0] + b0, c[mi][ni][1] + b1);
                float2 v1 = make_float2(c[mi][ni][2] + b0, c[mi][ni][3] + b1);
                *(float2*)(C + (size_t)row * N + col)       = v0;
                *(float2*)(C + (size_t)(row + 8) * N + col) = v1;
            }
        }
    }
}

// ---------------------------------------------------------------------------
// HMMA flash attention, pure cp.async loads of pre-split bf16 qkv.
// Q-tile 128, K-tile 64 (double-buffered), 8 warps (16 q-rows each).
// Q pre-scaled by 0.125 in the GEMM epilogue.  V via ldmatrix.trans.
// ---------------------------------------------------------------------------
#define QT 128
#define KT 64
#define APAD 72
#define Q_HALVES  (QT * APAD)
#define KV_HALVES (KT * APAD)
#define STG_HALVES (4 * KV_HALVES)
#define ATT_SMEM ((2 * Q_HALVES + 2 * STG_HALVES) * 2)   // 110592 B

__global__ __launch_bounds__(256)
void attn_hmma_kernel(const __nv_bfloat16* __restrict__ qh,
                      const __nv_bfloat16* __restrict__ ql,
                      __nv_bfloat16* __restrict__ ch,
                      __nv_bfloat16* __restrict__ cl) {
    extern __shared__ char smc[];
    const uint32_t sbase = smem_u32(smc);
    const uint32_t sQh = sbase;
    const uint32_t sQl = sbase + Q_HALVES * 2;

    const int qt = blockIdx.x, h = blockIdx.y, b = blockIdx.z;
    const int tid = threadIdx.x, lane = tid & 31, w = tid >> 5;
    const int q0 = qt * QT;
    const size_t tok0 = (size_t)b * SEQ;

    // ---- Q tile: 128 rows x 64 halves = 8 segs of 16B per row ----
#pragma unroll
    for (int it = 0; it < 4; it++) {
        const int i = tid + it * 256;          // 0..1023
        const int r = i >> 3, seg = i & 7;
        const size_t g = (tok0 + q0 + r) * DIM3 + h * HD + seg * 8;
        const uint32_t off = (r * APAD + seg * 8) * 2;
        cp16(sQh + off, qh + g);
        cp16(sQl + off, ql + g);
    }

    // ---- K/V stage loader: 64 rows x 8 segs = 512 cp16 per array ----
    auto load_kv = [&](int s, int kt) {
        const uint32_t st = sbase + (2 * Q_HALVES + s * STG_HALVES) * 2;
#pragma unroll
        for (int it = 0; it < 2; it++) {
            const int i = tid + it * 256;      // 0..511
            const int r = i >> 3, seg = i & 7;
            const size_t g = (tok0 + kt * KT + r) * DIM3 + h * HD + seg * 8;
            const uint32_t off = (r * APAD + seg * 8) * 2;
            cp16(st + off,                      qh + g + DIM_OUT);       // Kh
            cp16(st + KV_HALVES * 2 + off,      ql + g + DIM_OUT);       // Kl
            cp16(st + 2 * KV_HALVES * 2 + off,  qh + g + 2 * DIM_OUT);   // Vh
            cp16(st + 3 * KV_HALVES * 2 + off,  ql + g + 2 * DIM_OUT);   // Vl
        }
    };

    load_kv(0, 0);
    CP_COMMIT();

    float o[8][4];
#pragma unroll
    for (int t = 0; t < 8; t++)
#pragma unroll
        for (int j = 0; j < 4; j++) o[t][j] = 0.0f;
    float mrow[2] = {-1e30f, -1e30f};
    float lrow[2] = {0.0f, 0.0f};

    const int nkt = (qt + 1) * 2;
    for (int kt = 0; kt < nkt; kt++) {
        if (kt + 1 < nkt) load_kv((kt + 1) & 1, kt + 1);
        CP_COMMIT();
        CP_WAIT1();
        __syncthreads();

        const uint32_t st  = sbase + (2 * Q_HALVES + (kt & 1) * STG_HALVES) * 2;
        const uint32_t sKh = st;
        const uint32_t sKl = st + KV_HALVES * 2;
        const uint32_t sVh = st + 2 * KV_HALVES * 2;
        const uint32_t sVl = st + 3 * KV_HALVES * 2;
        const int k0 = kt * KT;

        // ---- S = Q @ K^T (3-term split), warp tile 16 x 64 ----
        float sc[8][4];
#pragma unroll
        for (int t = 0; t < 8; t++)
#pragma unroll
            for (int j = 0; j < 4; j++) sc[t][j] = 0.0f;

#pragma unroll
        for (int ks = 0; ks < 4; ks++) {
            const int arow = w * 16 + (lane & 15);
            const int acol = ks * 16 + (lane >> 4) * 8;
            uint32_t ah[4], al[4];
            ldsm4(ah, sQh + (arow * APAD + acol) * 2);
            ldsm4(al, sQl + (arow * APAD + acol) * 2);
            uint32_t bh[8][2], bl[8][2];
            const int bn = ((lane >> 3) & 1) * 8 + (lane & 7);
#pragma unroll
            for (int np = 0; np < 4; np++) {
                const uint32_t off = ((np * 16 + bn) * APAD + acol) * 2;
                uint32_t r[4];
                ldsm4(r, sKh + off);
                bh[np * 2 + 0][0] = r[0]; bh[np * 2 + 0][1] = r[2];
                bh[np * 2 + 1][0] = r[1]; bh[np * 2 + 1][1] = r[3];
                ldsm4(r, sKl + off);
                bl[np * 2 + 0][0] = r[0]; bl[np * 2 + 0][1] = r[2];
                bl[np * 2 + 1][0] = r[1]; bl[np * 2 + 1][1] = r[3];
            }
#pragma unroll
            for (int t = 0; t < 8; t++) {
                mma16816(sc[t], ah, bh[t]);
                mma16816(sc[t], ah, bl[t]);
                mma16816(sc[t], al, bh[t]);
            }
        }

        // ---- causal mask (near-diagonal tiles only) ----
        const int row0 = q0 + w * 16 + (lane >> 2);
        if (k0 + KT - 1 > q0 + w * 16) {
#pragma unroll
            for (int t = 0; t < 8; t++) {
                const int col = k0 + t * 8 + (lane & 3) * 2;
                if (col     > row0)     sc[t][0] = -1e30f;
                if (col + 1 > row0)     sc[t][1] = -1e30f;
                if (col     > row0 + 8) sc[t][2] = -1e30f;
                if (col + 1 > row0 + 8) sc[t][3] = -1e30f;
            }
        }

        // ---- online softmax ----
#pragma unroll
        for (int rh = 0; rh < 2; rh++) {
            const int i0 = rh * 2;
            float mx = -1e30f;
#pragma unroll
            for (int t = 0; t < 8; t++)
                mx = fmaxf(mx, fmaxf(sc[t][i0], sc[t][i0 + 1]));
            mx = fmaxf(mx, __shfl_xor_sync(0xffffffffu, mx, 1));
            mx = fmaxf(mx, __shfl_xor_sync(0xffffffffu, mx, 2));
            const float mn = fmaxf(mrow[rh], mx);
            const float alpha = __expf(mrow[rh] - mn);
            float rs = 0.0f;
#pragma unroll
            for (int t = 0; t < 8; t++) {
                const float p0 = __expf(sc[t][i0] - mn);
                const float p1 = __expf(sc[t][i0 + 1] - mn);
                sc[t][i0] = p0; sc[t][i0 + 1] = p1;
                rs += p0 + p1;
            }
            rs += __shfl_xor_sync(0xffffffffu, rs, 1);
            rs += __shfl_xor_sync(0xffffffffu, rs, 2);
            lrow[rh] = lrow[rh] * alpha + rs;
            mrow[rh] = mn;
#pragma unroll
            for (int t = 0; t < 8; t++) { o[t][i0] *= alpha; o[t][i0 + 1] *= alpha; }
        }

        // ---- O += P @ V (3-term split); V via ldmatrix.trans ----
#pragma unroll
        for (int ks = 0; ks < 4; ks++) {
            uint32_t ph[4], pl[4];
            split_pack(sc[2 * ks][0],     sc[2 * ks][1],     ph[0], pl[0]);
            split_pack(sc[2 * ks][2],     sc[2 * ks][3],     ph[1], pl[1]);
            split_pack(sc[2 * ks + 1][0], sc[2 * ks + 1][1], ph[2], pl[2]);
            split_pack(sc[2 * ks + 1][2], sc[2 * ks + 1][3], ph[3], pl[3]);

            uint32_t vh[8][2], vl[8][2];
            // V stored [kv][d] row-major; trans-ldsm yields .col B frags:
            //   M0={kv0-7,d lo}->r0, M1={kv8-15,d lo}->r1,
            //   M2={kv0-7,d hi}->r2, M3={kv8-15,d hi}->r3
            const int kvrow = ks * 16 + (lane & 15);
            const int dcol  = (lane >> 4) * 8;
#pragma unroll
            for (int np = 0; np < 4; np++) {
                const uint32_t off = (kvrow * APAD + np * 16 + dcol) * 2;
                uint32_t r[4];
                ldsm4t(r, sVh + off);
                vh[np * 2 + 0][0] = r[0]; vh[np * 2 + 0][1] = r[1];
                vh[np * 2 + 1][0] = r[2]; vh[np * 2 + 1][1] = r[3];
                ldsm4t(r, sVl + off);
                vl[np * 2 + 0][0] = r[0]; vl[np * 2 + 0][1] = r[1];
                vl[np * 2 + 1][0] = r[2]; vl[np * 2 + 1][1] = r[3];
            }
#pragma unroll
            for (int t = 0; t < 8; t++) {
                mma16816(o[t], ph, vh[t]);
                mma16816(o[t], ph, vl[t]);
                mma16816(o[t], pl, vh[t]);
            }
        }
        __syncthreads();
    }

    // ---- normalize + split-write ctx ----
    const float inv0 = 1.0f / lrow[0];
    const float inv1 = 1.0f / lrow[1];
    const size_t row0 = tok0 + q0 + w * 16 + (lane >> 2);
#pragma unroll
    for (int t = 0; t < 8; t++) {
        const int col = h * HD + t * 8 + (lane & 3) * 2;
        uint32_t hi, lo;
        split_pack(o[t][0] * inv0, o[t][1] * inv0, hi, lo);
        *(uint32_t*)(ch + row0 * DIM_OUT + col) = hi;
        *(uint32_t*)(cl + row0 * DIM_OUT + col) = lo;
        split_pack(o[t][2] * inv1, o[t][3] * inv1, hi, lo);
        *(uint32_t*)(ch + (row0 + 8) * DIM_OUT + col) = hi;
        *(uint32_t*)(cl + (row0 + 8) * DIM_OUT + col) = lo;
    }
}

// ---------------------------------------------------------------------------
extern "C" void kernel_launch(void* const* d_in, const int* in_sizes, int n_in,
                              void* d_out, int out_size) {
    const float* X     = (const float*)d_in[0];
    const float* W_qkv = (const float*)d_in[1];
    const float* W_out = (const float*)d_in[2];
    const float* b_out = (const float*)d_in[3];
    float* out = (float*)d_out;

    __nv_bfloat16 *qkvh, *qkvl, *xh, *xl, *ch, *cl, *wqh, *wql, *woh, *wol;
    cudaGetSymbolAddress((void**)&qkvh, g_qkvh);
    cudaGetSymbolAddress((void**)&qkvl, g_qkvl);
    cudaGetSymbolAddress((void**)&xh,  g_Xh);
    cudaGetSymbolAddress((void**)&xl,  g_Xl);
    cudaGetSymbolAddress((void**)&ch,  g_Ch);
    cudaGetSymbolAddress((void**)&cl,  g_Cl);
    cudaGetSymbolAddress((void**)&wqh, g_Wqkv_h);
    cudaGetSymbolAddress((void**)&wql, g_Wqkv_l);
    cudaGetSymbolAddress((void**)&woh, g_Wout_h);
    cudaGetSymbolAddress((void**)&wol, g_Wout_l);

    cudaFuncSetAttribute(hmma_gemm_kernel,
                         cudaFuncAttributeMaxDynamicSharedMemorySize, GEMM_SMEM);
    cudaFuncSetAttribute(attn_hmma_kernel,
                         cudaFuncAttributeMaxDynamicSharedMemorySize, ATT_SMEM);

    // 0) weight transpose+split, X split
    {
        dim3 blk(32, 8);
        transpose_split_kernel<<<dim3(DIM3 / 32, DIM_IN / 32), blk>>>(
            W_qkv, DIM_IN, DIM3, wqh, wql);
        transpose_split_kernel<<<dim3(DIM_OUT / 32, DIM_OUT / 32), blk>>>(
            W_out, DIM_OUT, DIM_OUT, woh, wol);
        const int n4 = NTOK * DIM_IN / 4;
        split_rows_kernel<<<(n4 + 255) / 256, 256>>>(
            (const float4*)X, n4, (uint2*)xh, (uint2*)xl);
    }

    // 1) QKV projection -> pre-split bf16 (Q columns pre-scaled by 0.125)
    hmma_gemm_kernel<<<dim3(DIM3 / BN, NTOK / BM), 256, GEMM_SMEM>>>(
        NTOK, DIM3, DIM_IN, xh, xl, wqh, wql,
        nullptr, nullptr, qkvh, qkvl, DIM_OUT);

    // 2) causal flash attention (HMMA split, cp.async) -> pre-split ctx
    attn_hmma_kernel<<<dim3(SEQ / QT, NHEADS, B_DIM), 256, ATT_SMEM>>>(
        qkvh, qkvl, ch, cl);

    // 3) out projection + bias -> fp32 output
    hmma_gemm_kernel<<<dim3(DIM_OUT / BN, NTOK / BM), 256, GEMM_SMEM>>>(
        NTOK, DIM_OUT, DIM_OUT, ch, cl, woh, wol,
        out, b_out, nullptr, nullptr, 0);
}